// round 9
// baseline (speedup 1.0000x reference)
#include <cuda_runtime.h>

// out[b, y, x] = in[b, y + dyi[b], x - dxi[b]] if in-bounds else 0
// B=1024, WIN=256, C=1, fp32.
//
// SMEM-staged: each CTA handles a 32-row tile of one batch.
//  Load phase : 8 aligned coalesced LDG.128 per thread (MLP=8), row shift by
//               index, invalid rows zero-filled into smem.
//  Store phase: warp-per-row scalar mapping -> stride-1 conflict-free LDS,
//               STG.32 with 32 consecutive lanes = full 128B lines.
// The x-misalignment is absorbed entirely by shared memory.

static constexpr int WIN       = 256;
static constexpr int B_        = 1024;
static constexpr int TILE_ROWS = 32;

__global__ __launch_bounds__(256) void translation_smem_kernel(
    const float4* __restrict__ in4,
    const float* __restrict__ dx,
    const float* __restrict__ dy,
    float* __restrict__ out)
{
    __shared__ float tile[TILE_ROWS * WIN];   // 32 KB

    int t   = threadIdx.x;
    int cta = blockIdx.x;
    int b   = cta >> 3;                 // 8 tiles per batch
    int ty  = (cta & 7) << 5;           // tile base row

    int dxi = (int)dx[b];               // trunc toward zero == astype(int32)
    int dyi = (int)dy[b];

    // ---- load phase: 2048 float4 per tile, 8 per thread, all independent
    const float4* src = in4 + (b << 14);        // b * 256 rows * 64 float4
    #pragma unroll
    for (int k = 0; k < 8; k++) {
        int i = t + (k << 8);                   // 0..2047
        int r = i >> 6;                         // tile row 0..31
        int c = i & 63;                         // float4 column
        int sy = ty + r + dyi;
        float4 v = make_float4(0.f, 0.f, 0.f, 0.f);
        if ((unsigned)sy < (unsigned)WIN)
            v = __ldcs(src + (sy << 6) + c);
        *reinterpret_cast<float4*>(&tile[(r << 8) + (c << 2)]) = v;
    }
    __syncthreads();

    // ---- store phase: warp w handles rows w, w+8, w+16, w+24
    int w = t >> 5;
    int l = t & 31;
    float* dstbase = out + ((((b << 8) | ty)) << 8);   // (b*256 + ty) * 256
    #pragma unroll
    for (int rr = 0; rr < 4; rr++) {
        int r = w + (rr << 3);
        const float* srow = &tile[r << 8];
        float* dst = dstbase + (r << 8);
        #pragma unroll
        for (int j = 0; j < 8; j++) {
            int x  = l + (j << 5);              // lanes consecutive -> 128B line
            int sx = x - dxi;
            float v = 0.f;
            if ((unsigned)sx < (unsigned)WIN) v = srow[sx];
            __stcs(dst + x, v);
        }
    }
}

extern "C" void kernel_launch(void* const* d_in, const int* in_sizes, int n_in,
                              void* d_out, int out_size)
{
    const float4* in  = (const float4*)d_in[0];
    const float*  dx  = (const float*)d_in[1];
    const float*  dy  = (const float*)d_in[2];
    float*        out = (float*)d_out;

    int blocks = B_ * (WIN / TILE_ROWS);   // 8192
    translation_smem_kernel<<<blocks, 256>>>(in, dx, dy, out);
}

// round 10
// speedup vs baseline: 1.1627x; 1.1627x over previous
#include <cuda_runtime.h>

// out[b, y, x] = in[b, y + dyi[b], x - dxi[b]] if in-bounds else 0
// B=1024, WIN=256, C=1, fp32.
//
// One warp per PAIR of adjacent rows. All 4 wide loads issued up front
// (MLP=4); then row 0 is fully processed and stored BEFORE row 1's select
// network is built, cutting peak register pressure vs the r4 version.
// __launch_bounds__(256,7) pins regs <=36 -> 87.5% theoretical occupancy.

static constexpr int WIN = 256;

__device__ __forceinline__ void emit_row(
    float4 a0, float4 a1, int s, int q0, int lane,
    const float4* __restrict__ src, bool rowok, int sx0,
    float4* __restrict__ dst)
{
    // a2 = next lane's a0 (lane 31 loads its own)
    float4 a2;
    a2.x = __shfl_down_sync(0xffffffffu, a0.x, 1);
    a2.y = __shfl_down_sync(0xffffffffu, a0.y, 1);
    a2.z = __shfl_down_sync(0xffffffffu, a0.z, 1);
    a2.w = __shfl_down_sync(0xffffffffu, a0.w, 1);
    if (lane == 31) {
        int c2 = q0 + 2 < 0 ? 0 : (q0 + 2 > 63 ? 63 : q0 + 2);
        a2 = __ldg(src + c2);
    }

    float4 o0, o1;
    if (s == 0)      { o0 = a0; o1 = a1; }
    else if (s == 1) { o0 = make_float4(a0.y, a0.z, a0.w, a1.x);
                       o1 = make_float4(a1.y, a1.z, a1.w, a2.x); }
    else if (s == 2) { o0 = make_float4(a0.z, a0.w, a1.x, a1.y);
                       o1 = make_float4(a1.z, a1.w, a2.x, a2.y); }
    else             { o0 = make_float4(a0.w, a1.x, a1.y, a1.z);
                       o1 = make_float4(a1.w, a2.x, a2.y, a2.z); }

    unsigned base = rowok ? (unsigned)sx0 : 0xC0000000u;
    if (base + 0u >= (unsigned)WIN) o0.x = 0.f;
    if (base + 1u >= (unsigned)WIN) o0.y = 0.f;
    if (base + 2u >= (unsigned)WIN) o0.z = 0.f;
    if (base + 3u >= (unsigned)WIN) o0.w = 0.f;
    if (base + 4u >= (unsigned)WIN) o1.x = 0.f;
    if (base + 5u >= (unsigned)WIN) o1.y = 0.f;
    if (base + 6u >= (unsigned)WIN) o1.z = 0.f;
    if (base + 7u >= (unsigned)WIN) o1.w = 0.f;

    dst[0] = o0;
    dst[1] = o1;
}

__global__ __launch_bounds__(256, 7) void translation_kernel(
    const float4* __restrict__ in4,
    const float* __restrict__ dx,
    const float* __restrict__ dy,
    float4* __restrict__ out4)
{
    int idx  = blockIdx.x * blockDim.x + threadIdx.x;
    int lane = idx & 31;
    int pair = idx >> 5;              // row pair index
    int b    = pair >> 7;             // 128 pairs per batch
    int y0   = (pair & 127) << 1;

    int dxi = (int)dx[b];             // trunc toward zero == astype(int32)
    int dyi = (int)dy[b];

    int sy0 = y0 + dyi;
    int sy1 = sy0 + 1;
    bool ok0 = (unsigned)sy0 < (unsigned)WIN;
    bool ok1 = (unsigned)sy1 < (unsigned)WIN;
    int syc0 = ok0 ? sy0 : 0;
    int syc1 = ok1 ? sy1 : 0;

    const float4* src0 = in4 + (((b << 8) | syc0) << 6);
    const float4* src1 = in4 + (((b << 8) | syc1) << 6);

    int x0  = lane << 3;
    int sx0 = x0 - dxi;
    int q0  = sx0 >> 2;
    int s   = sx0 & 3;                // warp-uniform

    int c0 = q0     < 0 ? 0 : (q0     > 63 ? 63 : q0);
    int c1 = q0 + 1 < 0 ? 0 : (q0 + 1 > 63 ? 63 : q0 + 1);

    // 4 independent wide loads up front (MLP=4)
    float4 A0 = __ldg(src0 + c0);
    float4 A1 = __ldg(src0 + c1);
    float4 B0 = __ldg(src1 + c0);
    float4 B1 = __ldg(src1 + c1);

    int row0 = (b << 8) | y0;
    float4* dst0 = out4 + (row0 << 6) + (lane << 1);

    // row 0 fully retired before row 1's temporaries are created
    emit_row(A0, A1, s, q0, lane, src0, ok0, sx0, dst0);
    emit_row(B0, B1, s, q0, lane, src1, ok1, sx0, dst0 + 64);
}

extern "C" void kernel_launch(void* const* d_in, const int* in_sizes, int n_in,
                              void* d_out, int out_size)
{
    const float4* in  = (const float4*)d_in[0];
    const float*  dx  = (const float*)d_in[1];
    const float*  dy  = (const float*)d_in[2];
    float4*       out = (float4*)d_out;

    // warps = B*WIN/2 = 131072 ; threads = 4,194,304
    int threads = 256;
    int blocks  = (1024 * 128 * 32) / threads;   // 16384
    translation_kernel<<<blocks, threads>>>(in, dx, dy, out);
}